// round 4
// baseline (speedup 1.0000x reference)
#include <cuda_runtime.h>
#include <cstdint>

// DilateAttention: B=4, d=384 (12 heads x 32), H=W=64, 3x3 kernel, dilation 2, zero pad 2.
// q,k,v: [B, 384, 64, 64] f32. out: [B, 64, 64, 384] f32.

#define NH  12
#define HD  32
#define HH  64
#define WW  64
#define TH  4
#define RR  (TH + 4)            // 8 rows incl. halo
#define CC  68                  // 64 cols + 2 zero-pad each side
#define TILE_FLOATS (HD * RR * CC)   // 17408
#define SMEM_FLOATS (TILE_FLOATS + 4)
#define SCALE 0.17677669529663689f   // 32^-0.5

__device__ __forceinline__ void cp_async16(uint32_t saddr, const void* gptr) {
    asm volatile("cp.async.cg.shared.global [%0], [%1], 16;\n" :: "r"(saddr), "l"(gptr));
}
__device__ __forceinline__ void cp_commit_wait() {
    asm volatile("cp.async.commit_group;\ncp.async.wait_group 0;\n" ::: "memory");
}

__global__ __launch_bounds__(256, 3)
void dilate_attn_kernel(const float* __restrict__ q,
                        const float* __restrict__ k,
                        const float* __restrict__ v,
                        float* __restrict__ out)
{
    extern __shared__ float smem[];
    // tile[c][r][cc] at smem+2: interior (cc=2) byte addr = row*272 + 16 -> 16B aligned every row
    float* tile = smem + 2;

    const int tx  = threadIdx.x;       // 0..63 = w
    const int ty  = threadIdx.y;       // 0..3
    const int tid = ty * 64 + tx;

    const int h0   = blockIdx.x * TH;
    const int bh   = blockIdx.y;       // 0..47
    const int b    = bh / NH;
    const int head = bh - b * NH;
    const size_t base = ((size_t)b * 384 + (size_t)head * HD) * (HH * WW);

    // ---- staging assignment: one k halo row per thread (32ch x 8rows = 256 rows) ----
    const int sc = tid >> 3;           // channel 0..31
    const int sr = tid & 7;            // halo row 0..7
    const int gh = h0 - 2 + sr;
    const int rowoff = (sc * RR + sr) * CC;
    const bool inb = (unsigned)gh < HH;
    const float* gk = k + base + (size_t)sc * (HH * WW) + gh * WW;
    const uint32_t s_int = (uint32_t)__cvta_generic_to_shared(&tile[rowoff + 2]);

    // ---- stage k tile (full 64-wide aligned rows via cp.async), zero pads ----
    if (inb) {
        #pragma unroll
        for (int j = 0; j < 16; j++) cp_async16(s_int + j * 16, gk + j * 4);
        tile[rowoff + 0] = 0.f; tile[rowoff + 1] = 0.f;
        tile[rowoff + 66] = 0.f; tile[rowoff + 67] = 0.f;
    } else {
        #pragma unroll
        for (int j = 0; j < CC; j++) tile[rowoff + j] = 0.f;
    }

    // q into registers while cp.async streams (coalesced: lane = consecutive w)
    const int h = h0 + ty;
    float qr[HD];
    {
        const float* qp = q + base + h * WW + tx;
        #pragma unroll
        for (int c = 0; c < HD; c++) qr[c] = qp[(size_t)c * (HH * WW)];
    }

    cp_commit_wait();
    __syncthreads();                   // the only CTA barrier

    // ---- logits over 9 dilated neighbors (k from smem) ----
    float lg[9];
    #pragma unroll
    for (int kp = 0; kp < 9; kp++) {
        const int di = kp / 3;
        const int dj = kp - di * 3;
        const int r  = ty + 2 * di;        // 0..7
        const int cc = tx + 2 * dj;        // 0..67
        const float* kr = &tile[r * CC + cc];
        float d0 = 0.f, d1 = 0.f;
        #pragma unroll
        for (int c = 0; c < HD; c += 2) {
            d0 = fmaf(qr[c],     kr[(c)     * (RR * CC)], d0);
            d1 = fmaf(qr[c + 1], kr[(c + 1) * (RR * CC)], d1);
        }
        lg[kp] = (d0 + d1) * SCALE;        // OOB neighbor -> k==0 -> logit 0 (matches zero-pad)
    }

    // ---- softmax over 9 ----
    float m = lg[0];
    #pragma unroll
    for (int kp = 1; kp < 9; kp++) m = fmaxf(m, lg[kp]);
    float p[9];
    float s = 0.f;
    #pragma unroll
    for (int kp = 0; kp < 9; kp++) { p[kp] = __expf(lg[kp] - m); s += p[kp]; }
    const float inv = __fdividef(1.f, s);

    // ---- weighted sum of v: direct predicated LDG (L1-resident, lane-coalesced) ----
    float acc[HD];
    #pragma unroll
    for (int c = 0; c < HD; c++) acc[c] = 0.f;

    #pragma unroll
    for (int kp = 0; kp < 9; kp++) {
        const int di = kp / 3;
        const int dj = kp - di * 3;
        const int gh2 = h  - 2 + 2 * di;   // -2..65
        const int gw2 = tx - 2 + 2 * dj;   // -2..65
        const bool ok = ((unsigned)gh2 < HH) && ((unsigned)gw2 < WW);
        const float pw = p[kp];
        const float* vp = v + base + (ptrdiff_t)(gh2 * WW + gw2);
        #pragma unroll
        for (int c = 0; c < HD; c++) {
            const float vv = ok ? __ldg(vp + (ptrdiff_t)c * (HH * WW)) : 0.f;
            acc[c] = fmaf(pw, vv, acc[c]);
        }
    }

    // ---- direct contiguous 128B store per thread (8 x STG.128, 16B aligned) ----
    const size_t obase = (((size_t)b * HH + h) * WW + tx) * 384 + (size_t)head * HD;
    float4* o4 = (float4*)(out + obase);
    #pragma unroll
    for (int i = 0; i < 8; i++) {
        float4 t;
        t.x = acc[4 * i + 0] * inv;
        t.y = acc[4 * i + 1] * inv;
        t.z = acc[4 * i + 2] * inv;
        t.w = acc[4 * i + 3] * inv;
        o4[i] = t;
    }
}

extern "C" void kernel_launch(void* const* d_in, const int* in_sizes, int n_in,
                              void* d_out, int out_size)
{
    const float* q = (const float*)d_in[0];
    const float* k = (const float*)d_in[1];
    const float* v = (const float*)d_in[2];
    float* out = (float*)d_out;

    const int smem_bytes = SMEM_FLOATS * sizeof(float);   // 69648
    cudaFuncSetAttribute(dilate_attn_kernel,
                         cudaFuncAttributeMaxDynamicSharedMemorySize, smem_bytes);

    dim3 block(64, 4, 1);
    dim3 grid(HH / TH, 4 * NH, 1);        // (16, 48)
    dilate_attn_kernel<<<grid, block, smem_bytes>>>(q, k, v, out);
}